// round 8
// baseline (speedup 1.0000x reference)
#include <cuda_runtime.h>

#define T_STEPS 1000
#define BATCH   4096
#define IN_SZ   8
#define HID     50
#define OUT_SZ  6
#define NT      64            // one batch element: rows 0..49 hidden, 50..55 out, 56..63 x-producers
#define VW      64            // v width: [r(50) | x(8) | pad(6)]
#define NPAIR   30            // 60-float weight row = 30 f32x2 pairs
#define DT_F    0.1f

typedef unsigned long long ull;

__device__ __forceinline__ ull pack2(float lo, float hi) {
    ull u; asm("mov.b64 %0, {%1, %2};" : "=l"(u) : "f"(lo), "f"(hi)); return u;
}
__device__ __forceinline__ void unpack2(ull u, float& lo, float& hi) {
    asm("mov.b64 {%0, %1}, %2;" : "=f"(lo), "=f"(hi) : "l"(u));
}
#define FMA2(acc, a, b) asm("fma.rn.f32x2 %0, %1, %2, %0;" : "+l"(acc) : "l"(a), "l"(b))
#define ADD2(d, a, b)   asm("add.rn.f32x2 %0, %1, %2;" : "=l"(d) : "l"(a), "l"(b))

__global__ void __launch_bounds__(NT, 10) biornn_kernel(
    const float* __restrict__ x,      // (T, B, 8)
    const float* __restrict__ Win,    // (50, 8)
    const float* __restrict__ Wrec,   // (50, 50)
    const float* __restrict__ bias,   // (50,)
    const float* __restrict__ Wow,    // (6, 50)
    const float* __restrict__ Wob,    // (6,)
    float* __restrict__ out)          // (T, B, 6)
{
    __shared__ __align__(16) float v_s[2][VW];

    const int row = threadIdx.x;      // 0..63
    const int b   = blockIdx.x;

    const bool is_hid  = (row < HID);
    const bool is_out  = (row >= HID) && (row < HID + OUT_SZ);
    const bool is_prod = (row >= 56);           // x producers (dead rows)

    // zero both v buffers (slots 58..63 stay 0 forever)
    for (int i = row; i < 2 * VW; i += NT) ((float*)v_s)[i] = 0.f;

    // ---- weight row (60 cols = [Wrec|Win] or [Wow|0]) packed into 30 ull ----
    ull wv[NPAIR];
    ull bjp;
    {
        if (is_hid) {
            const float* wr = Wrec + row * HID;
#pragma unroll
            for (int i = 0; i < 25; i++) wv[i] = pack2(wr[2 * i], wr[2 * i + 1]);
            const float* wi = Win + row * IN_SZ;
#pragma unroll
            for (int i = 0; i < 4; i++) wv[25 + i] = pack2(wi[2 * i], wi[2 * i + 1]);
            wv[29] = 0ULL;
            bjp = pack2(bias[row], 0.f);
        } else if (is_out) {
            const float* wo = Wow + (row - HID) * HID;
#pragma unroll
            for (int i = 0; i < 25; i++) wv[i] = pack2(wo[2 * i], wo[2 * i + 1]);
#pragma unroll
            for (int i = 25; i < NPAIR; i++) wv[i] = 0ULL;
            bjp = pack2(Wob[row - HID], 0.f);
        } else {
#pragma unroll
            for (int i = 0; i < NPAIR; i++) wv[i] = 0ULL;
            bjp = 0ULL;
        }
    }

    // ---- x producer state: thread row=56+i owns x[t][b][i] ----
    const int xi = row - 56;                       // 0..7 for producers
    const float* xptr = x + (size_t)b * IN_SZ + (is_prod ? xi : 0);
    const size_t XS = (size_t)BATCH * IN_SZ;       // elements per step
    float xA = 0.f, xB = 0.f;
    if (is_prod) {
        xA = xptr[0];                              // x_0
        xB = xptr[XS];                             // x_1
    }
    // STS slot: hidden rows -> row; producers -> 50+xi (= row-6)
    const int sts_slot = is_hid ? row : (row - 6);
    const bool do_sts  = is_hid || is_prod;

    float* op = out + (is_out ? ((size_t)b * OUT_SZ + (row - HID)) : 0);

    const ulonglong2* const vp0 = reinterpret_cast<const ulonglong2*>(&v_s[0][0]);
    const ulonglong2* const vp1 = reinterpret_cast<const ulonglong2*>(&v_s[1][0]);
    float* const sb0 = &v_s[0][0];
    float* const sb1 = &v_s[1][0];

    float h = 0.f;

    __syncthreads();

    int buf = 0;
#pragma unroll 1
    for (int t = 0; t < T_STEPS; t++) {
        // publish this step's v entries: r = relu(h) and x_t
        if (do_sts) {
            float val = is_hid ? fmaxf(h, 0.f) : xA;
            (buf ? sb1 : sb0)[sts_slot] = val;
        }

        __syncthreads();

        // producers fetch x_{t+2} (clamped) — 2 steps of latency cover
        if (is_prod) {
            xA = xB;
            const int t2 = (t + 2 < T_STEPS) ? (t + 2) : (T_STEPS - 1);
            xB = xptr[(size_t)t2 * XS];
        }

        // dot(weight_row, v) — all lanes of warp read same address (broadcast)
        const ulonglong2* vp = buf ? vp1 : vp0;
        ull a0 = bjp, a1 = 0ULL;
#pragma unroll
        for (int kk = 0; kk < 15; kk++) {          // 15 x LDS.128 -> 30 FMA2
            const ulonglong2 v2 = vp[kk];
            FMA2(a0, wv[2 * kk],     v2.x);
            FMA2(a1, wv[2 * kk + 1], v2.y);
        }
        ADD2(a0, a0, a1);
        float sl, sh;
        unpack2(a0, sl, sh);
        const float s = sl + sh;

        if (is_out) {
            *op = s;                               // y_t
            op += BATCH * OUT_SZ;
        }
        h = fmaf(DT_F, s - h, h);                  // h += DT*(acc - h); dead/out rows: garbage, unused

        buf ^= 1;
    }
}

extern "C" void kernel_launch(void* const* d_in, const int* in_sizes, int n_in,
                              void* d_out, int out_size) {
    const float* x    = (const float*)d_in[0];
    const float* Win  = (const float*)d_in[1];
    const float* Wrec = (const float*)d_in[2];
    const float* bias = (const float*)d_in[3];
    const float* Wow  = (const float*)d_in[4];
    const float* Wob  = (const float*)d_in[5];
    float* out = (float*)d_out;

    biornn_kernel<<<BATCH, NT>>>(x, Win, Wrec, bias, Wow, Wob, out);
}

// round 9
// speedup vs baseline: 1.5809x; 1.5809x over previous
#include <cuda_runtime.h>

#define T_STEPS 1000
#define BATCH   4096
#define IN_SZ   8
#define HID     50
#define OUT_SZ  6
#define NT      64            // one batch element: rows 0..49 hid, 50..55 out, 56..63 x-producers
#define VW      64            // v storage width; dot product reads cols 0..59
#define NPAIR   30            // 60-col weight row = 30 f32x2 pairs (60 regs)
#define DT_F    0.1f

typedef unsigned long long ull;

__device__ __forceinline__ ull pack2(float lo, float hi) {
    ull u; asm("mov.b64 %0, {%1, %2};" : "=l"(u) : "f"(lo), "f"(hi)); return u;
}
__device__ __forceinline__ void unpack2(ull u, float& lo, float& hi) {
    asm("mov.b64 {%0, %1}, %2;" : "=f"(lo), "=f"(hi) : "l"(u));
}
#define FMA2(acc, a, b) asm("fma.rn.f32x2 %0, %1, %2, %0;" : "+l"(acc) : "l"(a), "l"(b))
#define ADD2(d, a, b)   asm("add.rn.f32x2 %0, %1, %2;" : "=l"(d) : "l"(a), "l"(b))

__global__ void __launch_bounds__(NT, 8) biornn_kernel(   // 128-reg ceiling: NO spill
    const float* __restrict__ x,      // (T, B, 8)
    const float* __restrict__ Win,    // (50, 8)
    const float* __restrict__ Wrec,   // (50, 50)
    const float* __restrict__ bias,   // (50,)
    const float* __restrict__ Wow,    // (6, 50)
    const float* __restrict__ Wob,    // (6,)
    float* __restrict__ out)          // (T, B, 6)
{
    __shared__ __align__(16) float v_s[2][VW];   // v = [r(50) | x(8) | dead(2 read as 0-weight) | dead(4 unread)]

    const int row = threadIdx.x;      // 0..63
    const int b   = blockIdx.x;

    const bool is_hid  = (row < HID);
    const bool is_out  = (row >= HID) && (row < HID + OUT_SZ);
    const bool is_prod = (row >= 56);

    for (int i = row; i < 2 * VW; i += NT) ((float*)v_s)[i] = 0.f;

    // ---- 60-col weight row packed into 30 ull pairs ----
    ull wv[NPAIR];
    ull bjp;
    if (is_hid) {
        const float* wr = Wrec + row * HID;
#pragma unroll
        for (int i = 0; i < 25; i++) wv[i] = pack2(wr[2 * i], wr[2 * i + 1]);
        const float* wi = Win + row * IN_SZ;
#pragma unroll
        for (int i = 0; i < 4; i++) wv[25 + i] = pack2(wi[2 * i], wi[2 * i + 1]);
        wv[29] = 0ULL;                                   // cols 58,59
        bjp = pack2(bias[row], 0.f);
    } else if (is_out) {
        const float* wo = Wow + (row - HID) * HID;
#pragma unroll
        for (int i = 0; i < 25; i++) wv[i] = pack2(wo[2 * i], wo[2 * i + 1]);
#pragma unroll
        for (int i = 25; i < NPAIR; i++) wv[i] = 0ULL;
        bjp = pack2(Wob[row - HID], 0.f);
    } else {
#pragma unroll
        for (int i = 0; i < NPAIR; i++) wv[i] = 0ULL;
        bjp = 0ULL;
    }

    // ---- branchless x pipeline: producers own x[t][b][row-56]; others read dummy x[t][b][0] ----
    const int xi = is_prod ? (row - 56) : 0;
    const float* xptr = x + (size_t)b * IN_SZ + xi;
    const size_t XS = (size_t)BATCH * IN_SZ;
    float xA = xptr[0];           // x_0
    float xB = xptr[XS];          // x_1
    xptr += 2 * XS;               // -> x_2

    // STS slot: hid -> row; prod -> 50+xi; out -> dead slots 58..63
    const int slot = is_hid ? row : (is_prod ? (row - 6) : (row + 8));

    float* op = out + (is_out ? ((size_t)b * OUT_SZ + (row - HID)) : 0);

    float*           sbA = &v_s[0][0];
    float*           sbB = &v_s[1][0];
    const ulonglong2* vpA = reinterpret_cast<const ulonglong2*>(&v_s[0][0]);
    const ulonglong2* vpB = reinterpret_cast<const ulonglong2*>(&v_s[1][0]);

    float h = 0.f;
    __syncthreads();

#pragma unroll 1
    for (int t = 0; t < T_STEPS; t++) {
        // publish this lane's v entry (every lane, every step — branchless)
        sbA[slot] = is_prod ? xA : fmaxf(h, 0.f);

        __syncthreads();

        // advance x pipeline: xA <- x_{t+1}, xB <- x_{t+2} (pointer clamped at end)
        xA = xB;
        xB = *xptr;
        if (t < T_STEPS - 3) xptr += XS;

        // dot(weight_row[0..59], v[0..59]) — 15 broadcast LDS.128, 4 acc chains
        ull a0 = bjp, b0 = 0ULL, a1 = 0ULL, b1 = 0ULL;
#pragma unroll
        for (int kk = 0; kk < 15; kk++) {
            const ulonglong2 v2 = vpA[kk];
            if (kk & 1) { FMA2(b0, wv[2 * kk], v2.x); FMA2(b1, wv[2 * kk + 1], v2.y); }
            else        { FMA2(a0, wv[2 * kk], v2.x); FMA2(a1, wv[2 * kk + 1], v2.y); }
        }
        ADD2(a0, a0, b0);
        ADD2(a1, a1, b1);
        ADD2(a0, a0, a1);
        float sl, sh;
        unpack2(a0, sl, sh);
        const float s = sl + sh;

        if (is_out) *op = s;                   // single predicated STG
        op += BATCH * OUT_SZ;

        h = fmaf(DT_F, s - h, h);              // garbage for non-hidden lanes; never read

        // swap double buffers
        float* ts = sbA; sbA = sbB; sbB = ts;
        const ulonglong2* tv = vpA; vpA = vpB; vpB = tv;
    }
}

extern "C" void kernel_launch(void* const* d_in, const int* in_sizes, int n_in,
                              void* d_out, int out_size) {
    const float* x    = (const float*)d_in[0];
    const float* Win  = (const float*)d_in[1];
    const float* Wrec = (const float*)d_in[2];
    const float* bias = (const float*)d_in[3];
    const float* Wow  = (const float*)d_in[4];
    const float* Wob  = (const float*)d_in[5];
    float* out = (float*)d_out;

    biornn_kernel<<<BATCH, NT>>>(x, Win, Wrec, bias, Wow, Wob, out);
}